// round 15
// baseline (speedup 1.0000x reference)
#include <cuda_runtime.h>

// Problem constants
#define Bq     8
#define Cq     128
#define HEADS  8
#define HC     16            // channels per head
#define Nq     16384         // H*W
#define NBH    (Bq*HEADS)    // 64

// Kernel-1 tiling (measured best: R11)
#define CHUNKS      16
#define CHUNK_COLS  (Nq/CHUNKS)        // 1024
#define TILE        128
#define NTILES      (CHUNK_COLS/TILE)  // 8
#define PAD         132                // row stride (528B = 33*16 -> 16B-aligned)

// Kernel-2 tiling: 1 column per thread, 256 threads -> 256 columns per block
#define COLS2       256

// Scratch (no allocations allowed -> __device__ globals)
__device__ float g_pctx[NBH][CHUNKS][HC][HC];   // unnormalized partial context
__device__ float g_psum[NBH][CHUNKS][HC];       // partial row sums of exp(k)

// ---- packed f32x2 helpers (ptxas never auto-fuses) ----
__device__ __forceinline__ unsigned long long fma2(unsigned long long a,
                                                   unsigned long long b,
                                                   unsigned long long c) {
    unsigned long long d;
    asm("fma.rn.f32x2 %0, %1, %2, %3;" : "=l"(d) : "l"(a), "l"(b), "l"(c));
    return d;
}
__device__ __forceinline__ unsigned long long pack2(float lo, float hi) {
    unsigned long long d;
    asm("mov.b64 %0, {%1, %2};" : "=l"(d) : "f"(lo), "f"(hi));
    return d;
}
__device__ __forceinline__ void unpack2(unsigned long long v, float& lo, float& hi) {
    asm("mov.b64 {%0, %1}, %2;" : "=f"(lo), "=f"(hi) : "l"(v));
}

// ---------------------------------------------------------------------------
// Kernel 1 (FROZEN at R11-measured form): per (b,h,chunk) partial
//   ctx'[r][c] = sum_n exp(k[r,n]) * v[c,n],  rowsum[r] = sum_n exp(k[r,n])
// 256 threads, double-buffered smem pipeline, one barrier per tile,
// f32x2-packed accumulation. Grid 1024 -> 4 CTAs/SM wave 1.
// ---------------------------------------------------------------------------
__global__ __launch_bounds__(256)
void ctx_partial_kernel(const float* __restrict__ x1, const float* __restrict__ x2) {
    __shared__ float e_sm[2][HC][PAD];
    __shared__ float v_sm[2][HC][PAD];
    __shared__ float red_sm[8 * 256];   // per-warp ctx partials
    __shared__ float rs_sm[256];        // per-thread row sums

    const int tid   = threadIdx.x;
    const int chunk = blockIdx.x;
    const int h     = blockIdx.y;
    const int b     = blockIdx.z;
    const int bh    = b * HEADS + h;

    const int base  = (b * Cq + h * HC) * Nq + chunk * CHUNK_COLS;
    const float* kptr = x2 + base;   // keys/queries come from x2
    const float* vptr = x1 + base;   // values come from x1

    const int pr = tid >> 4;   // producer row (0..15)
    const int pl = tid & 15;   // producer lane within row
    const int w  = tid >> 5;   // warp id (0..7)
    const int l  = tid & 31;
    const int rg = l >> 3;     // row group: rows rg*4 .. rg*4+3
    const int cg = l & 7;      // col group: cols cg*2, cg*2+1

    unsigned long long accp[4][2];   // packed partial-pair accumulators
    #pragma unroll
    for (int a = 0; a < 4; a++) { accp[a][0] = 0ull; accp[a][1] = 0ull; }
    float rowsum = 0.f;

    const int t4a = pl;            // float4 index 0..15
    const int t4b = pl + 16;       // float4 index 16..31

    float4 kv0, kv1, vv0, vv1;     // staging registers for the in-flight tile

    // ---- prologue: load + stage tile 0 into buffer 0 ----
    {
        const int off = pr * Nq;
        kv0 = *(const float4*)(kptr + off + 4 * t4a);
        kv1 = *(const float4*)(kptr + off + 4 * t4b);
        vv0 = *(const float4*)(vptr + off + 4 * t4a);
        vv1 = *(const float4*)(vptr + off + 4 * t4b);
        float4 e0, e1;
        e0.x = __expf(kv0.x); e0.y = __expf(kv0.y); e0.z = __expf(kv0.z); e0.w = __expf(kv0.w);
        e1.x = __expf(kv1.x); e1.y = __expf(kv1.y); e1.z = __expf(kv1.z); e1.w = __expf(kv1.w);
        rowsum += e0.x + e0.y + e0.z + e0.w + e1.x + e1.y + e1.z + e1.w;
        *(float4*)&e_sm[0][pr][4 * t4a] = e0;
        *(float4*)&e_sm[0][pr][4 * t4b] = e1;
        *(float4*)&v_sm[0][pr][4 * t4a] = vv0;
        *(float4*)&v_sm[0][pr][4 * t4b] = vv1;
    }
    __syncthreads();

    for (int tile = 0; tile < NTILES; tile++) {
        const int cur = tile & 1;
        const int nxt = cur ^ 1;

        // ---- issue loads for tile+1 (latency hidden by consume below) ----
        if (tile + 1 < NTILES) {
            const int off = pr * Nq + (tile + 1) * TILE;
            kv0 = *(const float4*)(kptr + off + 4 * t4a);
            kv1 = *(const float4*)(kptr + off + 4 * t4b);
            vv0 = *(const float4*)(vptr + off + 4 * t4a);
            vv1 = *(const float4*)(vptr + off + 4 * t4b);
        }

        // ---- consume tile from smem buffer `cur` (f32x2-packed FMAs) ----
        #pragma unroll
        for (int tb = 0; tb < 16; tb += 4) {
            const int t = w * 16 + tb;   // 16B-aligned (t % 4 == 0)
            ulonglong2 er2[4], vc2[2];
            #pragma unroll
            for (int jr = 0; jr < 4; jr++)
                er2[jr] = *(const ulonglong2*)&e_sm[cur][rg * 4 + jr][t];
            #pragma unroll
            for (int jc = 0; jc < 2; jc++)
                vc2[jc] = *(const ulonglong2*)&v_sm[cur][cg * 2 + jc][t];
            #pragma unroll
            for (int jr = 0; jr < 4; jr++) {
                #pragma unroll
                for (int jc = 0; jc < 2; jc++) {
                    accp[jr][jc] = fma2(er2[jr].x, vc2[jc].x, accp[jr][jc]);
                    accp[jr][jc] = fma2(er2[jr].y, vc2[jc].y, accp[jr][jc]);
                }
            }
        }

        // ---- stage tile+1 into buffer `nxt` (safe: last read fenced at t-1) ----
        if (tile + 1 < NTILES) {
            float4 e0, e1;
            e0.x = __expf(kv0.x); e0.y = __expf(kv0.y); e0.z = __expf(kv0.z); e0.w = __expf(kv0.w);
            e1.x = __expf(kv1.x); e1.y = __expf(kv1.y); e1.z = __expf(kv1.z); e1.w = __expf(kv1.w);
            rowsum += e0.x + e0.y + e0.z + e0.w + e1.x + e1.y + e1.z + e1.w;
            *(float4*)&e_sm[nxt][pr][4 * t4a] = e0;
            *(float4*)&e_sm[nxt][pr][4 * t4b] = e1;
            *(float4*)&v_sm[nxt][pr][4 * t4a] = vv0;
            *(float4*)&v_sm[nxt][pr][4 * t4b] = vv1;
        }
        __syncthreads();
    }

    // ---- block epilogue: horizontal add, reduce 8 warp-tiles, write partials ----
    #pragma unroll
    for (int jr = 0; jr < 4; jr++)
        #pragma unroll
        for (int jc = 0; jc < 2; jc++) {
            float lo, hi;
            unpack2(accp[jr][jc], lo, hi);
            red_sm[w * 256 + (rg * 4 + jr) * 16 + (cg * 2 + jc)] = lo + hi;
        }
    rs_sm[tid] = rowsum;
    __syncthreads();

    float p = 0.f;
    #pragma unroll
    for (int ww = 0; ww < 8; ww++) p += red_sm[ww * 256 + tid];
    g_pctx[bh][chunk][tid >> 4][tid & 15] = p;

    if (tid < HC) {
        float s = 0.f;
        #pragma unroll
        for (int j = 0; j < 16; j++) s += rs_sm[tid * 16 + j];
        g_psum[bh][chunk][tid] = s;
    }
}

// ---------------------------------------------------------------------------
// Kernel 2 (fused reduce + attend, 1 column per thread for max TLP):
//   ctx[k][v]  = (sum_chunk pctx) / (sum_chunk psum[k])   [inline, L2-hot]
//   out[v][n]  = (sum_k ctx[k][v] * exp(k[k,n])) / (sum_k exp(k[k,n]))
// Accumulators packed over the v-dimension (8 x f32x2 = 16 regs); ctx pairs
// come straight from smem via broadcast LDS.128. ~40 regs -> 5 CTAs/SM.
// Loads/stores: 32 lanes x 4B = 128B contiguous per row, fully coalesced.
// ---------------------------------------------------------------------------
__global__ __launch_bounds__(256, 5)
void attend_kernel(const float* __restrict__ x2, float* __restrict__ out) {
    __shared__ float ctx_sm[HC][HC];   // normalized ctx[k][v], rows 64B
    __shared__ float sinv_sm[HC];

    const int tid = threadIdx.x;
    const int h   = blockIdx.y;
    const int b   = blockIdx.z;
    const int bh  = b * HEADS + h;

    // ---- inline reduce of K1 partials (all reads L2-hot) ----
    if (tid < HC) {
        float s = 0.f;
        #pragma unroll
        for (int c = 0; c < CHUNKS; c++) s += g_psum[bh][c][tid];
        sinv_sm[tid] = 1.0f / s;
    }
    float a = 0.f;
    #pragma unroll
    for (int c = 0; c < CHUNKS; c++)
        a += ((const float*)g_pctx[bh][c])[tid];       // coalesced per chunk
    __syncthreads();
    ctx_sm[tid >> 4][tid & 15] = a * sinv_sm[tid >> 4];

    const int nn = blockIdx.x * COLS2 + tid;
    const float* kbase = x2  + (b * Cq + h * HC) * Nq + nn;
    float*       obase = out + (b * Cq + h * HC) * Nq + nn;
    __syncthreads();

    // 8 packed {v, v+1} accumulator pairs for this thread's single column
    unsigned long long acc[8];
    #pragma unroll
    for (int j = 0; j < 8; j++) acc[j] = 0ull;
    float s = 0.f;

    #pragma unroll
    for (int k = 0; k < HC; k++) {
        const float e = __expf(kbase[k * Nq]);
        s += e;
        const unsigned long long e2 = pack2(e, e);
        #pragma unroll
        for (int v = 0; v < HC; v += 4) {
            // {ctx[k][v],ctx[k][v+1]},{ctx[k][v+2],ctx[k][v+3]} in one LDS.128
            ulonglong2 c2 = *(const ulonglong2*)&ctx_sm[k][v];
            acc[v / 2]     = fma2(e2, c2.x, acc[v / 2]);
            acc[v / 2 + 1] = fma2(e2, c2.y, acc[v / 2 + 1]);
        }
    }

    const float r = 1.0f / s;
    #pragma unroll
    for (int j = 0; j < 8; j++) {
        float a0, a1;
        unpack2(acc[j], a0, a1);   // rows 2j, 2j+1
        obase[(2 * j)     * Nq] = a0 * r;
        obase[(2 * j + 1) * Nq] = a1 * r;
    }
}

// ---------------------------------------------------------------------------
extern "C" void kernel_launch(void* const* d_in, const int* in_sizes, int n_in,
                              void* d_out, int out_size) {
    const float* x1 = (const float*)d_in[0];   // values
    const float* x2 = (const float*)d_in[1];   // keys / queries
    float* out = (float*)d_out;

    ctx_partial_kernel<<<dim3(CHUNKS, HEADS, Bq), 256>>>(x1, x2);
    attend_kernel<<<dim3(Nq / COLS2, HEADS, Bq), 256>>>(x2, out);
}